// round 8
// baseline (speedup 1.0000x reference)
#include <cuda_runtime.h>
#include <cuda_fp16.h>
#include <cstdint>

// ============================================================================
// out = gelu( x @ ((fc1_w^T @ fc2_w^T + b) * mask) )   — fp32 in/out
// fp16 mma.sync.m16n8k16 path. R8: occupancy push — 3 CTAs/SM
// (launch_bounds(256,3), reg cap 85), 2-stage cp.async, JIT B fragments.
// ============================================================================

__device__ __half g_xh[49152 * 1024];
__device__ __half g_fc1T[1024 * 4096];
__device__ __half g_fc2h[1024 * 4096];
__device__ float  g_part[4 * 1024 * 1024];
__device__ __half g_attnT[1024 * 1024];

// ---------------- helpers ---------------------------------------------------
__device__ __forceinline__ uint32_t smem_u32(const void* p) {
    uint32_t a;
    asm("{ .reg .u64 t; cvta.to.shared.u64 t, %1; cvt.u32.u64 %0, t; }" : "=r"(a) : "l"(p));
    return a;
}
#define CP_ASYNC16(sdst, gsrc) \
    asm volatile("cp.async.cg.shared.global [%0], [%1], 16;" :: "r"(sdst), "l"(gsrc) : "memory")
#define CP_COMMIT() asm volatile("cp.async.commit_group;" ::: "memory")
#define CP_WAIT0()  asm volatile("cp.async.wait_group 0;" ::: "memory")
#define SWZ128(off) ((off) ^ (((off) >> 3) & 0x70))

__device__ __forceinline__ void ldsm_x4(uint32_t* r, uint32_t addr) {
    asm volatile("ldmatrix.sync.aligned.m8n8.x4.shared.b16 {%0,%1,%2,%3}, [%4];"
                 : "=r"(r[0]), "=r"(r[1]), "=r"(r[2]), "=r"(r[3]) : "r"(addr));
}
// fp16 MMA, fp32 accumulate: C[16x8] += A[16x16] * B[16x8]
__device__ __forceinline__ void mma_f16(float c[4], const uint32_t a[4], const uint32_t* b) {
    asm volatile(
        "mma.sync.aligned.m16n8k16.row.col.f32.f16.f16.f32 "
        "{%0,%1,%2,%3}, {%4,%5,%6,%7}, {%8,%9}, {%0,%1,%2,%3};"
        : "+f"(c[0]), "+f"(c[1]), "+f"(c[2]), "+f"(c[3])
        : "r"(a[0]), "r"(a[1]), "r"(a[2]), "r"(a[3]), "r"(b[0]), "r"(b[1]));
}
__device__ __forceinline__ float gelu_exact(float u) {
    return 0.5f * u * (1.0f + erff(u * 0.7071067811865476f));
}

// ---------------------------------------------------------------------------
// fp16 GEMM: CTA 128(m) x 128(n), 256 threads, warp tile 32x64.
// K chunks of 64 halfs (128B rows, SW128), 2-stage cp.async, 3 CTAs/SM.
// A [*,lda], B [*,ldb] k-major halfs, C = A·B^T fp32.
// EPI=1: gelu store; EPI=0: raw store. blockIdx.z = split-K slice.
// ---------------------------------------------------------------------------
constexpr int STAGES = 2;
constexpr int TBYTES = 128 * 128;   // 128 rows x 64 halfs

template <int EPI>
__global__ __launch_bounds__(256, 3) void hgemm(
    const __half* __restrict__ A, const __half* __restrict__ B, float* __restrict__ C,
    int M, int N, int lda, int ldb, int kSplit)
{
    extern __shared__ __align__(1024) char smem[];
    const uint32_t sb = smem_u32(smem);
    const int tid  = threadIdx.x;
    const int lane = tid & 31;
    const int wid  = tid >> 5;
    const int wm   = (wid & 3) * 32;
    const int wn   = (wid >> 2) * 64;
    const size_t bm = (size_t)blockIdx.y * 128;
    const size_t bn = (size_t)blockIdx.x * 128;

    const __half* Ab = A + (size_t)blockIdx.z * kSplit;
    const __half* Bb = B + (size_t)blockIdx.z * kSplit;

    const int nk = kSplit / 64;

    const int lr = tid >> 3;        // 0..31
    const int lc = tid & 7;         // 16B (8-half) column
    auto issue = [&](int chunk) {
        const int buf = chunk & 1;
        const uint32_t aBase = sb + buf * TBYTES;
        const uint32_t bBase = sb + STAGES * TBYTES + buf * TBYTES;
        const __half* ga = Ab + (bm + lr) * (size_t)lda + chunk * 64 + lc * 8;
        const __half* gb = Bb + (bn + lr) * (size_t)ldb + chunk * 64 + lc * 8;
#pragma unroll
        for (int j = 0; j < 4; j++) {
            CP_ASYNC16(aBase + SWZ128((lr + j * 32) * 128 + lc * 16), ga + (size_t)(j * 32) * lda);
            CP_ASYNC16(bBase + SWZ128((lr + j * 32) * 128 + lc * 16), gb + (size_t)(j * 32) * ldb);
        }
        CP_COMMIT();
    };

    float c[2][8][4];
#pragma unroll
    for (int im = 0; im < 2; im++)
#pragma unroll
        for (int in = 0; in < 8; in++)
#pragma unroll
            for (int q = 0; q < 4; q++) c[im][in][q] = 0.0f;

    issue(0);

    // ldmatrix addressing (see R6): A x4 = 16m x 16k frag in mma reg order;
    // B x4 = 16n x 16k -> {b0(n0-7), b1(n0-7), b0(n8-15), b1(n8-15)}.
    const int aRow = lane & 15;
    const int aKo  = ((lane >> 4) & 1) * 16;
    const int bRow = (lane & 7) + ((lane >> 4) << 3);
    const int bKo  = ((lane >> 3) & 1) * 16;

    for (int i = 0; i < nk; i++) {
        CP_WAIT0();
        __syncthreads();            // chunk i landed; buf (i-1)&1 fully consumed
        if (i + 1 < nk) issue(i + 1);

        const int buf = i & 1;
        const uint32_t aS = sb + buf * TBYTES;
        const uint32_t bS = sb + STAGES * TBYTES + buf * TBYTES;

#pragma unroll
        for (int ks = 0; ks < 4; ks++) {   // 4 x k16 (32B each) per 128B chunk
            uint32_t af[2][4];
#pragma unroll
            for (int im = 0; im < 2; im++)
                ldsm_x4(af[im], aS + SWZ128((wm + im * 16 + aRow) * 128 + ks * 32 + aKo));
#pragma unroll
            for (int nb = 0; nb < 4; nb++) {
                uint32_t bf[4];            // JIT B fragment: short live range
                ldsm_x4(bf, bS + SWZ128((wn + nb * 16 + bRow) * 128 + ks * 32 + bKo));
#pragma unroll
                for (int im = 0; im < 2; im++) {
                    mma_f16(c[im][nb * 2 + 0], af[im], &bf[0]);
                    mma_f16(c[im][nb * 2 + 1], af[im], &bf[2]);
                }
            }
        }
        __syncthreads();            // all warps done reading buf before next overwrite
    }

    // ---------------- epilogue ----------------
    float* Cb = C + (size_t)blockIdx.z * ((size_t)M * N);
    const int g  = lane >> 2;
    const int tg = lane & 3;
#pragma unroll
    for (int im = 0; im < 2; im++) {
#pragma unroll
        for (int in = 0; in < 8; in++) {
            const size_t r0 = bm + wm + im * 16 + g;
            const size_t r1 = r0 + 8;
            const size_t cc = bn + wn + in * 8 + tg * 2;
            float v0 = c[im][in][0], v1 = c[im][in][1];
            float v2 = c[im][in][2], v3 = c[im][in][3];
            if (EPI == 1) {
                v0 = gelu_exact(v0); v1 = gelu_exact(v1);
                v2 = gelu_exact(v2); v3 = gelu_exact(v3);
            }
            *reinterpret_cast<float2*>(Cb + r0 * N + cc) = make_float2(v0, v1);
            *reinterpret_cast<float2*>(Cb + r1 * N + cc) = make_float2(v2, v3);
        }
    }
}

// --------------- fp32 -> fp16 conversion pass --------------------------------
__global__ __launch_bounds__(256) void cvt_half(const float4* __restrict__ in,
                                                __half2* __restrict__ out, int n4)
{
    int i = blockIdx.x * 256 + threadIdx.x;
    int stride = gridDim.x * 256;
    for (; i < n4; i += stride) {
        float4 v = in[i];
        out[i * 2 + 0] = __floats2half2_rn(v.x, v.y);
        out[i * 2 + 1] = __floats2half2_rn(v.z, v.w);
    }
}

// ------- fc1 transpose + cvt: [4096,1024] f32 -> [1024,4096] half ------------
__global__ void transpose_k(const float* __restrict__ in, __half* __restrict__ out,
                            int R, int Cc)
{
    __shared__ float t[32][33];
    int bx = blockIdx.x * 32;
    int by = blockIdx.y * 32;
    int x = threadIdx.x, y = threadIdx.y;
#pragma unroll
    for (int j = 0; j < 32; j += 8)
        t[y + j][x] = in[(size_t)(by + y + j) * Cc + bx + x];
    __syncthreads();
#pragma unroll
    for (int j = 0; j < 32; j += 8)
        out[(size_t)(bx + y + j) * R + by + x] = __float2half_rn(t[x][y + j]);
}

// fixup: attnT[t][s] = half( (sum_sk part[sk][s][t] + bias[t]) * mask[s][t] )
__global__ void fixup_k(const float* __restrict__ part, const float* __restrict__ bias,
                        const float* __restrict__ mask, __half* __restrict__ attnT)
{
    __shared__ float t[32][33];
    int bt = blockIdx.x * 32;
    int bs = blockIdx.y * 32;
    int x = threadIdx.x, y = threadIdx.y;
#pragma unroll
    for (int j = 0; j < 32; j += 8) {
        int s = bs + y + j, tc = bt + x;
        size_t idx = (size_t)s * 1024 + tc;
        float v = part[idx] + part[idx + 1048576] + part[idx + 2097152] + part[idx + 3145728];
        v = (v + bias[tc]) * mask[idx];
        t[y + j][x] = v;
    }
    __syncthreads();
#pragma unroll
    for (int j = 0; j < 32; j += 8)
        attnT[(size_t)(bt + y + j) * 1024 + bs + x] = __float2half_rn(t[x][y + j]);
}

// ---------------------------------------------------------------------------
extern "C" void kernel_launch(void* const* d_in, const int* in_sizes, int n_in,
                              void* d_out, int out_size)
{
    const float* x    = (const float*)d_in[0];
    const float* fc1  = (const float*)d_in[1];
    const float* fc2  = (const float*)d_in[2];
    const float* bias = (const float*)d_in[3];
    const float* mask = (const float*)d_in[4];
    float* out = (float*)d_out;

    __half *xh, *fc1T, *fc2h, *attnT;
    float* part;
    cudaGetSymbolAddress((void**)&xh, g_xh);
    cudaGetSymbolAddress((void**)&fc1T, g_fc1T);
    cudaGetSymbolAddress((void**)&fc2h, g_fc2h);
    cudaGetSymbolAddress((void**)&part, g_part);
    cudaGetSymbolAddress((void**)&attnT, g_attnT);

    constexpr int SMEM = 2 * STAGES * TBYTES;   // 65536
    cudaFuncSetAttribute(hgemm<0>, cudaFuncAttributeMaxDynamicSharedMemorySize, SMEM);
    cudaFuncSetAttribute(hgemm<1>, cudaFuncAttributeMaxDynamicSharedMemorySize, SMEM);

    // fp32 -> fp16 operand conversion
    cvt_half<<<4736, 256>>>((const float4*)x, (__half2*)xh, 49152 * 1024 / 4);
    cvt_half<<<1024, 256>>>((const float4*)fc2, (__half2*)fc2h, 1024 * 4096 / 4);

    // fc1T[s][d] = half(fc1[d][s])
    transpose_k<<<dim3(32, 128), dim3(32, 8)>>>(fc1, fc1T, 4096, 1024);

    // GEMM1 split-K=4: part[sk] = fc1T · fc2h^T over k slice
    hgemm<0><<<dim3(8, 8, 4), 256, SMEM>>>(fc1T, fc2h, part,
                                           1024, 1024, 4096, 4096, 1024);

    // reduce + bias + mask + transpose -> attnT [t][s] half
    fixup_k<<<dim3(32, 32), dim3(32, 8)>>>(part, bias, mask, attnT);

    // GEMM2: out = gelu(xh · attnT^T)
    hgemm<1><<<dim3(8, 384, 1), 256, SMEM>>>(xh, attnT, out,
                                             49152, 1024, 1024, 1024, 1024);
}

// round 9
// speedup vs baseline: 1.5763x; 1.5763x over previous
#include <cuda_runtime.h>
#include <cuda_fp16.h>
#include <cstdint>

// ============================================================================
// out = gelu( x @ ((fc1_w^T @ fc2_w^T + b) * mask) )   — fp32 in/out
// fp16 mma.sync.m16n8k16. R9: 4 warps/CTA @ 64x64 warp tile (33% fewer LDSM
// per MMA, 2x per-warp MMA ILP). 3-stage cp.async + wait_group(1) as in R7.
// ============================================================================

__device__ __half g_xh[49152 * 1024];
__device__ __half g_fc1T[1024 * 4096];
__device__ __half g_fc2h[1024 * 4096];
__device__ float  g_part[4 * 1024 * 1024];
__device__ __half g_attnT[1024 * 1024];

// ---------------- helpers ---------------------------------------------------
__device__ __forceinline__ uint32_t smem_u32(const void* p) {
    uint32_t a;
    asm("{ .reg .u64 t; cvta.to.shared.u64 t, %1; cvt.u32.u64 %0, t; }" : "=r"(a) : "l"(p));
    return a;
}
#define CP_ASYNC16(sdst, gsrc) \
    asm volatile("cp.async.cg.shared.global [%0], [%1], 16;" :: "r"(sdst), "l"(gsrc) : "memory")
#define CP_COMMIT() asm volatile("cp.async.commit_group;" ::: "memory")
#define CP_WAIT1()  asm volatile("cp.async.wait_group 1;" ::: "memory")
#define CP_WAIT0()  asm volatile("cp.async.wait_group 0;" ::: "memory")
#define SWZ128(off) ((off) ^ (((off) >> 3) & 0x70))

__device__ __forceinline__ void ldsm_x4(uint32_t* r, uint32_t addr) {
    asm volatile("ldmatrix.sync.aligned.m8n8.x4.shared.b16 {%0,%1,%2,%3}, [%4];"
                 : "=r"(r[0]), "=r"(r[1]), "=r"(r[2]), "=r"(r[3]) : "r"(addr));
}
// fp16 MMA, fp32 accumulate: C[16x8] += A[16x16] * B[16x8]
__device__ __forceinline__ void mma_f16(float c[4], const uint32_t a[4], const uint32_t* b) {
    asm volatile(
        "mma.sync.aligned.m16n8k16.row.col.f32.f16.f16.f32 "
        "{%0,%1,%2,%3}, {%4,%5,%6,%7}, {%8,%9}, {%0,%1,%2,%3};"
        : "+f"(c[0]), "+f"(c[1]), "+f"(c[2]), "+f"(c[3])
        : "r"(a[0]), "r"(a[1]), "r"(a[2]), "r"(a[3]), "r"(b[0]), "r"(b[1]));
}
__device__ __forceinline__ float gelu_exact(float u) {
    return 0.5f * u * (1.0f + erff(u * 0.7071067811865476f));
}

// ---------------------------------------------------------------------------
// fp16 GEMM: CTA 128(m) x 128(n), 128 threads (4 warps), warp tile 64x64.
// K chunks of 64 halfs (128B rows, SW128), 3-stage cp.async, wait_group(1).
// A [*,lda], B [*,ldb] k-major halfs, C = A·B^T fp32.
// EPI=1: gelu store; EPI=0: raw store. blockIdx.z = split-K slice.
// ---------------------------------------------------------------------------
constexpr int STAGES = 3;
constexpr int TBYTES = 128 * 128;   // 128 rows x 64 halfs

template <int EPI>
__global__ __launch_bounds__(128, 2) void hgemm(
    const __half* __restrict__ A, const __half* __restrict__ B, float* __restrict__ C,
    int M, int N, int lda, int ldb, int kSplit)
{
    extern __shared__ __align__(1024) char smem[];
    const uint32_t sb = smem_u32(smem);
    const int tid  = threadIdx.x;
    const int lane = tid & 31;
    const int wid  = tid >> 5;           // 0..3
    const int wm   = (wid & 1) * 64;
    const int wn   = (wid >> 1) * 64;
    const size_t bm = (size_t)blockIdx.y * 128;
    const size_t bn = (size_t)blockIdx.x * 128;

    const __half* Ab = A + (size_t)blockIdx.z * kSplit;
    const __half* Bb = B + (size_t)blockIdx.z * kSplit;

    const int nk = kSplit / 64;

    const int lr = tid >> 3;        // 0..15
    const int lc = tid & 7;         // 16B (8-half) column
    auto issue = [&](int chunk) {
        const int buf = chunk % STAGES;
        const uint32_t aBase = sb + buf * TBYTES;
        const uint32_t bBase = sb + STAGES * TBYTES + buf * TBYTES;
        const __half* ga = Ab + (bm + lr) * (size_t)lda + chunk * 64 + lc * 8;
        const __half* gb = Bb + (bn + lr) * (size_t)ldb + chunk * 64 + lc * 8;
#pragma unroll
        for (int j = 0; j < 8; j++) {
            CP_ASYNC16(aBase + SWZ128((lr + j * 16) * 128 + lc * 16), ga + (size_t)(j * 16) * lda);
            CP_ASYNC16(bBase + SWZ128((lr + j * 16) * 128 + lc * 16), gb + (size_t)(j * 16) * ldb);
        }
        CP_COMMIT();
    };

    float c[4][8][4];   // [im: 4x16m][in: 8x8n][frag]
#pragma unroll
    for (int im = 0; im < 4; im++)
#pragma unroll
        for (int in = 0; in < 8; in++)
#pragma unroll
            for (int q = 0; q < 4; q++) c[im][in][q] = 0.0f;

    issue(0);
    issue(1);

    // ldmatrix addressing (see R6): A x4 = 16m x 16k frag in mma reg order;
    // B x4 = 16n x 16k -> {b0(n0-7), b1(n0-7), b0(n8-15), b1(n8-15)}.
    const int aRow = lane & 15;
    const int aKo  = ((lane >> 4) & 1) * 16;
    const int bRow = (lane & 7) + ((lane >> 4) << 3);
    const int bKo  = ((lane >> 3) & 1) * 16;

    for (int i = 0; i < nk; i++) {
        if (i + 1 < nk) { CP_WAIT1(); } else { CP_WAIT0(); }
        __syncthreads();
        if (i + 2 < nk) issue(i + 2);

        const int buf = i % STAGES;
        const uint32_t aS = sb + buf * TBYTES;
        const uint32_t bS = sb + STAGES * TBYTES + buf * TBYTES;

#pragma unroll
        for (int ks = 0; ks < 4; ks++) {   // 4 x k16 (32B each) per 128B chunk
            uint32_t af[4][4];
#pragma unroll
            for (int im = 0; im < 4; im++)
                ldsm_x4(af[im], aS + SWZ128((wm + im * 16 + aRow) * 128 + ks * 32 + aKo));
#pragma unroll
            for (int nb = 0; nb < 4; nb++) {
                uint32_t bf[4];
                ldsm_x4(bf, bS + SWZ128((wn + nb * 16 + bRow) * 128 + ks * 32 + bKo));
#pragma unroll
                for (int im = 0; im < 4; im++) {
                    mma_f16(c[im][nb * 2 + 0], af[im], &bf[0]);
                    mma_f16(c[im][nb * 2 + 1], af[im], &bf[2]);
                }
            }
        }
    }

    // ---------------- epilogue ----------------
    float* Cb = C + (size_t)blockIdx.z * ((size_t)M * N);
    const int g  = lane >> 2;
    const int tg = lane & 3;
#pragma unroll
    for (int im = 0; im < 4; im++) {
#pragma unroll
        for (int in = 0; in < 8; in++) {
            const size_t r0 = bm + wm + im * 16 + g;
            const size_t r1 = r0 + 8;
            const size_t cc = bn + wn + in * 8 + tg * 2;
            float v0 = c[im][in][0], v1 = c[im][in][1];
            float v2 = c[im][in][2], v3 = c[im][in][3];
            if (EPI == 1) {
                v0 = gelu_exact(v0); v1 = gelu_exact(v1);
                v2 = gelu_exact(v2); v3 = gelu_exact(v3);
            }
            *reinterpret_cast<float2*>(Cb + r0 * N + cc) = make_float2(v0, v1);
            *reinterpret_cast<float2*>(Cb + r1 * N + cc) = make_float2(v2, v3);
        }
    }
}

// --------------- fp32 -> fp16 conversion pass --------------------------------
__global__ __launch_bounds__(256) void cvt_half(const float4* __restrict__ in,
                                                __half2* __restrict__ out, int n4)
{
    int i = blockIdx.x * 256 + threadIdx.x;
    int stride = gridDim.x * 256;
    for (; i < n4; i += stride) {
        float4 v = in[i];
        out[i * 2 + 0] = __floats2half2_rn(v.x, v.y);
        out[i * 2 + 1] = __floats2half2_rn(v.z, v.w);
    }
}

// ------- fc1 transpose + cvt: [4096,1024] f32 -> [1024,4096] half ------------
__global__ void transpose_k(const float* __restrict__ in, __half* __restrict__ out,
                            int R, int Cc)
{
    __shared__ float t[32][33];
    int bx = blockIdx.x * 32;
    int by = blockIdx.y * 32;
    int x = threadIdx.x, y = threadIdx.y;
#pragma unroll
    for (int j = 0; j < 32; j += 8)
        t[y + j][x] = in[(size_t)(by + y + j) * Cc + bx + x];
    __syncthreads();
#pragma unroll
    for (int j = 0; j < 32; j += 8)
        out[(size_t)(bx + y + j) * R + by + x] = __float2half_rn(t[x][y + j]);
}

// fixup: attnT[t][s] = half( (sum_sk part[sk][s][t] + bias[t]) * mask[s][t] )
__global__ void fixup_k(const float* __restrict__ part, const float* __restrict__ bias,
                        const float* __restrict__ mask, __half* __restrict__ attnT)
{
    __shared__ float t[32][33];
    int bt = blockIdx.x * 32;
    int bs = blockIdx.y * 32;
    int x = threadIdx.x, y = threadIdx.y;
#pragma unroll
    for (int j = 0; j < 32; j += 8) {
        int s = bs + y + j, tc = bt + x;
        size_t idx = (size_t)s * 1024 + tc;
        float v = part[idx] + part[idx + 1048576] + part[idx + 2097152] + part[idx + 3145728];
        v = (v + bias[tc]) * mask[idx];
        t[y + j][x] = v;
    }
    __syncthreads();
#pragma unroll
    for (int j = 0; j < 32; j += 8)
        attnT[(size_t)(bt + y + j) * 1024 + bs + x] = __float2half_rn(t[x][y + j]);
}

// ---------------------------------------------------------------------------
extern "C" void kernel_launch(void* const* d_in, const int* in_sizes, int n_in,
                              void* d_out, int out_size)
{
    const float* x    = (const float*)d_in[0];
    const float* fc1  = (const float*)d_in[1];
    const float* fc2  = (const float*)d_in[2];
    const float* bias = (const float*)d_in[3];
    const float* mask = (const float*)d_in[4];
    float* out = (float*)d_out;

    __half *xh, *fc1T, *fc2h, *attnT;
    float* part;
    cudaGetSymbolAddress((void**)&xh, g_xh);
    cudaGetSymbolAddress((void**)&fc1T, g_fc1T);
    cudaGetSymbolAddress((void**)&fc2h, g_fc2h);
    cudaGetSymbolAddress((void**)&part, g_part);
    cudaGetSymbolAddress((void**)&attnT, g_attnT);

    constexpr int SMEM = 2 * STAGES * TBYTES;   // 98304
    cudaFuncSetAttribute(hgemm<0>, cudaFuncAttributeMaxDynamicSharedMemorySize, SMEM);
    cudaFuncSetAttribute(hgemm<1>, cudaFuncAttributeMaxDynamicSharedMemorySize, SMEM);

    // fp32 -> fp16 operand conversion
    cvt_half<<<4736, 256>>>((const float4*)x, (__half2*)xh, 49152 * 1024 / 4);
    cvt_half<<<1024, 256>>>((const float4*)fc2, (__half2*)fc2h, 1024 * 4096 / 4);

    // fc1T[s][d] = half(fc1[d][s])
    transpose_k<<<dim3(32, 128), dim3(32, 8)>>>(fc1, fc1T, 4096, 1024);

    // GEMM1 split-K=4: part[sk] = fc1T · fc2h^T over k slice
    hgemm<0><<<dim3(8, 8, 4), 128, SMEM>>>(fc1T, fc2h, part,
                                           1024, 1024, 4096, 4096, 1024);

    // reduce + bias + mask + transpose -> attnT [t][s] half
    fixup_k<<<dim3(32, 32), dim3(32, 8)>>>(part, bias, mask, attnT);

    // GEMM2: out = gelu(xh · attnT^T)
    hgemm<1><<<dim3(8, 384, 1), 128, SMEM>>>(xh, attnT, out,
                                             49152, 1024, 1024, 1024, 1024);
}